// round 15
// baseline (speedup 1.0000x reference)
#include <cuda_runtime.h>
#include <math.h>

// Problem constants (fixed by setup_inputs)
#define NB    16
#define NH    76
#define NW    76
#define NCH   32          // 19 + NC
#define HW    (NH*NW)     // 5776
#define NL    21          // 2*NK + 3
#define TX    16
#define TY    8
#define TPB   (TX*TY)                    // 128
#define GXN   ((NW + TX - 1) / TX)       // 5
#define GYN   ((NH + TY - 1) / TY)       // 10
#define NBLK  (GXN * GYN * NB)           // 800
#define KSTR  56                         // target-dim padding

#define FULLM 0xffffffffu
// Bias making every cull quantity strictly positive -> float order == uint-bit order
#define KBIAS 1024.0f

__device__ float        g_partials[NBLK];
__device__ unsigned int g_count;   // zero at load; last block subtracts NBLK (replay-safe)

__device__ __forceinline__ float fsigmoid(float x) {
    return 1.0f / (1.0f + __expf(-x));
}
__device__ __forceinline__ void l2_prefetch(const float* p) {
    asm volatile("prefetch.global.L2 [%0];" :: "l"(p));
}

__global__ void __launch_bounds__(TPB, 6)
loss_kernel(const float* __restrict__ out,
            const float* __restrict__ dst,
            const float* __restrict__ tgt,
            float* __restrict__ res)
{
    __shared__ float2   s_gt[9][KSTR];    // target corners in pixels, corner-major
    __shared__ unsigned s_mask[2];
    __shared__ int      s_map[TPB];       // packed (t+1)<<8 | cls for targeted cells
    __shared__ float    s_red[TPB / 32];
    __shared__ bool     s_last;

    const int b    = blockIdx.z;
    const int tid  = threadIdx.x;
    const int lane = tid & 31;
    const float* T = tgt + (size_t)b * (50 * NL);

    // Cell geometry first so prefetches can fire immediately
    const int  bx0  = blockIdx.x * TX, by0 = blockIdx.y * TY;
    const int  i    = bx0 + (tid & (TX - 1));
    const int  j    = by0 + (tid >> 4);
    const bool inb  = (i < NW) && (j < NH);
    const int  cell = inb ? (j * NW + i) : 0;            // clamp: conservative box growth
    const float* O  = out + (size_t)b * NCH * HW + cell; // channel stride HW
    const float* D  = dst + (size_t)b * NCH * HW + cell;

    // Fire-and-forget L2 prefetch of all 20 cell channels (no regs, no scoreboard)
    #pragma unroll
    for (int c = 0; c < 19; c++) l2_prefetch(O + (size_t)c * HW);
    l2_prefetch(D + (size_t)18 * HW);

    s_map[tid] = 0;

    // Phase 1: target corner staging, no div/mod — thread handles half a target
    if (tid < 100) {
        const int t    = tid >> 1;
        const int half = tid & 1;
        const float* row = T + t * NL;
        const int k0 = half ? 5 : 0;
        const int k1 = half ? 9 : 5;
        for (int k = k0; k < k1; k++) {
            float gx = row[1 + 2 * k] * 640.0f;
            float gy = row[2 + 2 * k] * 480.0f;
            s_gt[k][t] = make_float2(gx, gy);
        }
    }
    if (tid < 64) {   // warps 0,1 full — ballot legal
        float xv = (tid < 50) ? T[tid * NL + 1] : 0.0f;
        unsigned m = __ballot_sync(FULLM, xv != 0.0f);
        if (lane == 0) s_mask[tid >> 5] = m;
    }
    __syncthreads();

    // nv = leading-valid prefix length (cumprod semantics)
    const unsigned m0v = s_mask[0], m1v = s_mask[1];
    int nv;
    if (~m0v)      nv = __ffs(~m0v) - 1;
    else if (~m1v) nv = 32 + __ffs(~m1v) - 1;
    else           nv = 64;
    if (nv > 50) nv = 50;

    // Phase 2: targeted-cell map (last valid t wins == max t wins)
    if (tid < nv) {
        int gi = (int)(T[tid * NL + 1] * (float)NW);
        int gj = (int)(T[tid * NL + 2] * (float)NH);
        int li = gi - bx0, lj = gj - by0;
        if (li >= 0 && li < TX && lj >= 0 && lj < TY)
            atomicMax(&s_map[lj * TX + li], ((tid + 1) << 8) | (int)T[tid * NL]);
    }
    __syncthreads();

    const float sX = 640.0f / (float)NW;
    const float sY = 480.0f / (float)NH;
    const float fi = (float)i, fj = (float)j;

    bool sil = false;
    float conf_raw = 0.0f, tconf_raw = 0.0f;

    const unsigned actm = __ballot_sync(FULLM, inb);
    if (actm) {   // warp-uniform: skip fully out-of-range warps
        // Batched loads (should now be L2-hot from the prefetch); fold into biased keys
        unsigned kx[9], ky[9];
        {
            float ax0 = fsigmoid(O[0]);
            float ay0 = fsigmoid(O[HW]);
            kx[0] = __float_as_uint(fmaf(ax0 + fi, sX, KBIAS));
            ky[0] = __float_as_uint(fmaf(ay0 + fj, sY, KBIAS));
        }
        #pragma unroll
        for (int k = 1; k < 9; k++) {
            float ax = O[(size_t)(2 * k    ) * HW];
            float ay = O[(size_t)(2 * k + 1) * HW];
            kx[k] = __float_as_uint(fmaf(ax + fi, sX, KBIAS));
            ky[k] = __float_as_uint(fmaf(ay + fj, sY, KBIAS));
        }
        conf_raw  = O[(size_t)18 * HW];
        tconf_raw = D[(size_t)18 * HW];

        // Per-thread min/max tree over 9 corners (uint order == float order, positive)
        unsigned lmnx = min(min(min(kx[0], kx[1]), min(kx[2], kx[3])),
                            min(min(kx[4], kx[5]), min(kx[6], min(kx[7], kx[8]))));
        unsigned lmxx = max(max(max(kx[0], kx[1]), max(kx[2], kx[3])),
                            max(max(kx[4], kx[5]), max(kx[6], max(kx[7], kx[8]))));
        unsigned lmny = min(min(min(ky[0], ky[1]), min(ky[2], ky[3])),
                            min(min(ky[4], ky[5]), min(ky[6], min(ky[7], ky[8]))));
        unsigned lmxy = max(max(max(ky[0], ky[1]), max(ky[2], ky[3])),
                            max(max(ky[4], ky[5]), max(ky[6], max(ky[7], ky[8]))));

        // Joint warp box: only 4 REDUX, then unbias + expand in float space
        const float lox = __uint_as_float(__reduce_min_sync(FULLM, lmnx)) - (KBIAS + 80.5f);
        const float hix = __uint_as_float(__reduce_max_sync(FULLM, lmxx)) - (KBIAS - 80.5f);
        const float loy = __uint_as_float(__reduce_min_sync(FULLM, lmny)) - (KBIAS + 80.5f);
        const float hiy = __uint_as_float(__reduce_max_sync(FULLM, lmxy)) - (KBIAS - 80.5f);

        // Per-lane target cull: survivor iff >=6 corners inside joint expanded box
        int cnt0 = 0, cnt1 = 0;
        const bool half2 = (nv > 32);
        #pragma unroll
        for (int k = 0; k < 9; k++) {
            float2 g = s_gt[k][lane];
            cnt0 += (g.x >= lox && g.x <= hix && g.y >= loy && g.y <= hiy) ? 1 : 0;
        }
        if (half2) {
            int t2 = lane + 32;
            #pragma unroll
            for (int k = 0; k < 9; k++) {
                float2 g = s_gt[k][t2 < 50 ? t2 : 0];   // ballot predicate masks garbage lanes
                cnt1 += (g.x >= lox && g.x <= hix && g.y >= loy && g.y <= hiy) ? 1 : 0;
            }
        }
        unsigned sm0 = __ballot_sync(FULLM, (lane < nv) && cnt0 >= 6);
        unsigned sm1 = half2 ? __ballot_sync(FULLM, (lane + 32 < nv) && cnt1 >= 6) : 0u;

        // Exact evaluation for rare survivors (warp-uniform branch)
        unsigned long long smask = (((unsigned long long)sm1) << 32) | sm0;
        if (smask) {
            do {
                int t = __ffsll(smask) - 1;
                smask &= smask - 1;
                float d2[9];
                int cnt = 0;
                #pragma unroll
                for (int k = 0; k < 9; k++) {
                    float2 gv = s_gt[k][t];
                    float dx = gv.x - (__uint_as_float(kx[k]) - KBIAS);  // unbias = pixel coord
                    float dy = gv.y - (__uint_as_float(ky[k]) - KBIAS);
                    d2[k] = fmaf(dx, dx, dy * dy);
                    cnt += (d2[k] < 6400.0f) ? 1 : 0;
                }
                if (cnt >= 6) {   // precise math; essentially never taken
                    float s = 0.0f;
                    #pragma unroll
                    for (int k = 0; k < 9; k++) {
                        float dist = sqrtf(d2[k]);
                        float c = (expf(2.0f * (1.0f - dist * (1.0f / 80.0f))) - 1.0f)
                                  * (1.0f / 6.3890560989306495f);   // 1/(e^2-1)
                        s += (dist < 80.0f) ? c : 0.0f;
                    }
                    if (s * (1.0f / 9.0f) > 0.6f) sil = true;
                }
            } while (smask);
        }
    }

    // Losses
    float loss = 0.0f;
    if (inb) {
        const float conf  = fsigmoid(conf_raw);
        const float tconf = fsigmoid(tconf_raw);
        const int   mpk      = s_map[tid];
        const bool  targeted = (mpk != 0);
        const int   tc       = mpk & 0xff;
        const float cm  = targeted ? 5.0f : (sil ? 0.0f : 1.0f);
        const float dcf = conf - tconf;
        loss = 0.5f * dcf * dcf * cm;

        if (targeted) {   // rare (~1 cell per target); O reloads are L1-hot
            float lc = 0.0f;
            {
                float d0 = fsigmoid(O[0])  - fsigmoid(D[0]);
                float d1 = fsigmoid(O[HW]) - fsigmoid(D[HW]);
                lc += d0 * d0 + d1 * d1;
            }
            #pragma unroll
            for (int c = 2; c < 18; c++) {
                float dd = O[(size_t)c * HW] - D[(size_t)c * HW];
                lc += dd * dd;
            }
            loss += 0.5f * lc;

            // class CE = logsumexp(logits) - logits[tcls]
            float l[13];
            #pragma unroll
            for (int c = 0; c < 13; c++) l[c] = O[(size_t)(19 + c) * HW];
            float mx = l[0];
            #pragma unroll
            for (int c = 1; c < 13; c++) mx = fmaxf(mx, l[c]);
            float se = 0.0f;
            #pragma unroll
            for (int c = 0; c < 13; c++) se += expf(l[c] - mx);
            loss += (mx + logf(se)) - l[tc];
        }
    }

    // Deterministic intra-block reduction (4 warps)
    #pragma unroll
    for (int off = 16; off; off >>= 1)
        loss += __shfl_down_sync(FULLM, loss, off);
    if (lane == 0) s_red[tid >> 5] = loss;
    __syncthreads();
    if (tid == 0) {
        float v = s_red[0] + s_red[1] + s_red[2] + s_red[3];
        g_partials[(blockIdx.z * GYN + blockIdx.y) * GXN + blockIdx.x] = v;
        __threadfence();
        unsigned old = atomicAdd(&g_count, 1u);
        s_last = (old == (unsigned)(NBLK - 1));
    }
    __syncthreads();

    // Last block: fixed-order final reduction (deterministic)
    if (s_last && tid < 32) {
        float s = 0.0f;
        for (int idx = tid; idx < NBLK; idx += 32)
            s += g_partials[idx];
        #pragma unroll
        for (int off = 16; off; off >>= 1)
            s += __shfl_down_sync(FULLM, s, off);
        if (tid == 0) {
            res[0] = s;
            atomicSub(&g_count, (unsigned)NBLK);   // replay-safe reset
        }
    }
}

extern "C" void kernel_launch(void* const* d_in, const int* in_sizes, int n_in,
                              void* d_out, int out_size)
{
    const float* out = (const float*)d_in[0];
    const float* dst = (const float*)d_in[1];
    const float* tgt = (const float*)d_in[2];
    (void)in_sizes; (void)n_in; (void)out_size;

    dim3 grid(GXN, GYN, NB);
    loss_kernel<<<grid, TPB>>>(out, dst, tgt, (float*)d_out);
}

// round 17
// speedup vs baseline: 1.2149x; 1.2149x over previous
#include <cuda_runtime.h>
#include <math.h>

// Problem constants (fixed by setup_inputs)
#define NB    16
#define NH    76
#define NW    76
#define NCH   32          // 19 + NC
#define HW    (NH*NW)     // 5776
#define NL    21          // 2*NK + 3
#define TX    16
#define TY    8
#define TPB   (TX*TY)                    // 128
#define GXN   ((NW + TX - 1) / TX)       // 5
#define GYN   ((NH + TY - 1) / TY)       // 10
#define NBLK  (GXN * GYN * NB)           // 800
#define KSTR  56                         // target-dim padding

#define FULLM 0xffffffffu
// Bias making every cull quantity strictly positive -> float order == uint-bit order
#define KBIAS 1024.0f

__device__ float        g_partials[NBLK];
__device__ unsigned int g_count;   // zero at load; last block subtracts NBLK (replay-safe)

__device__ __forceinline__ float fsigmoid(float x) {
    return 1.0f / (1.0f + __expf(-x));
}

__global__ void __launch_bounds__(TPB, 6)
loss_kernel(const float* __restrict__ out,
            const float* __restrict__ dst,
            const float* __restrict__ tgt,
            float* __restrict__ res)
{
    __shared__ float2   s_gt[9][KSTR];    // target corners in pixels, corner-major
    __shared__ unsigned s_mask[2];
    __shared__ int      s_map[TPB];       // packed (t+1)<<8 | cls for targeted cells
    __shared__ float    s_red[TPB / 32];
    __shared__ bool     s_last;

    const int b    = blockIdx.z;
    const int tid  = threadIdx.x;
    const int lane = tid & 31;
    const float* T = tgt + (size_t)b * (50 * NL);

    s_map[tid] = 0;

    // Phase 1: target corner staging, no div/mod — thread handles half a target
    if (tid < 100) {
        const int t    = tid >> 1;
        const int half = tid & 1;
        const float* row = T + t * NL;
        const int k0 = half ? 5 : 0;
        const int k1 = half ? 9 : 5;
        for (int k = k0; k < k1; k++) {
            float gx = row[1 + 2 * k] * 640.0f;
            float gy = row[2 + 2 * k] * 480.0f;
            s_gt[k][t] = make_float2(gx, gy);
        }
    }
    if (tid < 64) {   // warps 0,1 full — ballot legal
        float xv = (tid < 50) ? T[tid * NL + 1] : 0.0f;
        unsigned m = __ballot_sync(FULLM, xv != 0.0f);
        if (lane == 0) s_mask[tid >> 5] = m;
    }
    __syncthreads();

    // nv = leading-valid prefix length (cumprod semantics)
    const unsigned m0v = s_mask[0], m1v = s_mask[1];
    int nv;
    if (~m0v)      nv = __ffs(~m0v) - 1;
    else if (~m1v) nv = 32 + __ffs(~m1v) - 1;
    else           nv = 64;
    if (nv > 50) nv = 50;

    // Phase 2: targeted-cell map (last valid t wins == max t wins)
    const int bx0 = blockIdx.x * TX, by0 = blockIdx.y * TY;
    if (tid < nv) {
        int gi = (int)(T[tid * NL + 1] * (float)NW);
        int gj = (int)(T[tid * NL + 2] * (float)NH);
        int li = gi - bx0, lj = gj - by0;
        if (li >= 0 && li < TX && lj >= 0 && lj < TY)
            atomicMax(&s_map[lj * TX + li], ((tid + 1) << 8) | (int)T[tid * NL]);
    }
    __syncthreads();

    const int  i    = bx0 + (tid & (TX - 1));
    const int  j    = by0 + (tid >> 4);
    const bool inb  = (i < NW) && (j < NH);
    const int  cell = inb ? (j * NW + i) : 0;            // clamp: conservative box growth
    const float* O  = out + (size_t)b * NCH * HW + cell; // channel stride HW
    const float* D  = dst + (size_t)b * NCH * HW + cell;

    const float sX = 640.0f / (float)NW;
    const float sY = 480.0f / (float)NH;
    const float fi = (float)i, fj = (float)j;

    bool sil = false;
    float conf_raw = 0.0f, tconf_raw = 0.0f;

    const unsigned actm = __ballot_sync(FULLM, inb);
    if (actm) {   // warp-uniform: skip fully out-of-range warps
        // Batched loads (post-sync, validated position); fold into biased keys
        unsigned kx[9], ky[9];
        {
            float ax0 = fsigmoid(O[0]);
            float ay0 = fsigmoid(O[HW]);
            kx[0] = __float_as_uint(fmaf(ax0 + fi, sX, KBIAS));
            ky[0] = __float_as_uint(fmaf(ay0 + fj, sY, KBIAS));
        }
        #pragma unroll
        for (int k = 1; k < 9; k++) {
            float ax = O[(size_t)(2 * k    ) * HW];
            float ay = O[(size_t)(2 * k + 1) * HW];
            kx[k] = __float_as_uint(fmaf(ax + fi, sX, KBIAS));
            ky[k] = __float_as_uint(fmaf(ay + fj, sY, KBIAS));
        }
        conf_raw  = O[(size_t)18 * HW];
        tconf_raw = D[(size_t)18 * HW];

        // Per-thread min/max tree over 9 corners (uint order == float order, positive)
        unsigned lmnx = min(min(min(kx[0], kx[1]), min(kx[2], kx[3])),
                            min(min(kx[4], kx[5]), min(kx[6], min(kx[7], kx[8]))));
        unsigned lmxx = max(max(max(kx[0], kx[1]), max(kx[2], kx[3])),
                            max(max(kx[4], kx[5]), max(kx[6], max(kx[7], kx[8]))));
        unsigned lmny = min(min(min(ky[0], ky[1]), min(ky[2], ky[3])),
                            min(min(ky[4], ky[5]), min(ky[6], min(ky[7], ky[8]))));
        unsigned lmxy = max(max(max(ky[0], ky[1]), max(ky[2], ky[3])),
                            max(max(ky[4], ky[5]), max(ky[6], max(ky[7], ky[8]))));

        // Joint warp box: only 4 REDUX, then unbias + expand in float space
        const float lox = __uint_as_float(__reduce_min_sync(FULLM, lmnx)) - (KBIAS + 80.5f);
        const float hix = __uint_as_float(__reduce_max_sync(FULLM, lmxx)) - (KBIAS - 80.5f);
        const float loy = __uint_as_float(__reduce_min_sync(FULLM, lmny)) - (KBIAS + 80.5f);
        const float hiy = __uint_as_float(__reduce_max_sync(FULLM, lmxy)) - (KBIAS - 80.5f);

        // Per-lane target cull: survivor iff >=6 corners inside joint expanded box
        int cnt0 = 0, cnt1 = 0;
        const bool half2 = (nv > 32);
        #pragma unroll
        for (int k = 0; k < 9; k++) {
            float2 g = s_gt[k][lane];
            cnt0 += (g.x >= lox && g.x <= hix && g.y >= loy && g.y <= hiy) ? 1 : 0;
        }
        if (half2) {
            int t2 = lane + 32;
            #pragma unroll
            for (int k = 0; k < 9; k++) {
                float2 g = s_gt[k][t2 < 50 ? t2 : 0];   // ballot predicate masks garbage lanes
                cnt1 += (g.x >= lox && g.x <= hix && g.y >= loy && g.y <= hiy) ? 1 : 0;
            }
        }
        unsigned sm0 = __ballot_sync(FULLM, (lane < nv) && cnt0 >= 6);
        unsigned sm1 = half2 ? __ballot_sync(FULLM, (lane + 32 < nv) && cnt1 >= 6) : 0u;

        // Exact evaluation for rare survivors (warp-uniform branch)
        unsigned long long smask = (((unsigned long long)sm1) << 32) | sm0;
        if (smask) {
            do {
                int t = __ffsll(smask) - 1;
                smask &= smask - 1;
                float d2[9];
                int cnt = 0;
                #pragma unroll
                for (int k = 0; k < 9; k++) {
                    float2 gv = s_gt[k][t];
                    float dx = gv.x - (__uint_as_float(kx[k]) - KBIAS);  // unbias = pixel coord
                    float dy = gv.y - (__uint_as_float(ky[k]) - KBIAS);
                    d2[k] = fmaf(dx, dx, dy * dy);
                    cnt += (d2[k] < 6400.0f) ? 1 : 0;
                }
                if (cnt >= 6) {   // precise math; essentially never taken
                    float s = 0.0f;
                    #pragma unroll
                    for (int k = 0; k < 9; k++) {
                        float dist = sqrtf(d2[k]);
                        float c = (expf(2.0f * (1.0f - dist * (1.0f / 80.0f))) - 1.0f)
                                  * (1.0f / 6.3890560989306495f);   // 1/(e^2-1)
                        s += (dist < 80.0f) ? c : 0.0f;
                    }
                    if (s * (1.0f / 9.0f) > 0.6f) sil = true;
                }
            } while (smask);
        }
    }

    // Losses
    float loss = 0.0f;
    if (inb) {
        const float conf  = fsigmoid(conf_raw);
        const float tconf = fsigmoid(tconf_raw);
        const int   mpk      = s_map[tid];
        const bool  targeted = (mpk != 0);
        const int   tc       = mpk & 0xff;
        const float cm  = targeted ? 5.0f : (sil ? 0.0f : 1.0f);
        const float dcf = conf - tconf;
        loss = 0.5f * dcf * dcf * cm;

        if (targeted) {   // rare (~1 cell per target); O reloads are L1-hot
            float lc = 0.0f;
            {
                float d0 = fsigmoid(O[0])  - fsigmoid(D[0]);
                float d1 = fsigmoid(O[HW]) - fsigmoid(D[HW]);
                lc += d0 * d0 + d1 * d1;
            }
            #pragma unroll
            for (int c = 2; c < 18; c++) {
                float dd = O[(size_t)c * HW] - D[(size_t)c * HW];
                lc += dd * dd;
            }
            loss += 0.5f * lc;

            // class CE = logsumexp(logits) - logits[tcls]
            float l[13];
            #pragma unroll
            for (int c = 0; c < 13; c++) l[c] = O[(size_t)(19 + c) * HW];
            float mx = l[0];
            #pragma unroll
            for (int c = 1; c < 13; c++) mx = fmaxf(mx, l[c]);
            float se = 0.0f;
            #pragma unroll
            for (int c = 0; c < 13; c++) se += expf(l[c] - mx);
            loss += (mx + logf(se)) - l[tc];
        }
    }

    // Deterministic intra-block reduction (4 warps)
    #pragma unroll
    for (int off = 16; off; off >>= 1)
        loss += __shfl_down_sync(FULLM, loss, off);
    if (lane == 0) s_red[tid >> 5] = loss;
    __syncthreads();
    if (tid == 0) {
        float v = s_red[0] + s_red[1] + s_red[2] + s_red[3];
        g_partials[(blockIdx.z * GYN + blockIdx.y) * GXN + blockIdx.x] = v;
        __threadfence();
        unsigned old = atomicAdd(&g_count, 1u);
        s_last = (old == (unsigned)(NBLK - 1));
    }
    __syncthreads();

    // Last block: fixed-order final reduction (deterministic)
    if (s_last && tid < 32) {
        float s = 0.0f;
        for (int idx = tid; idx < NBLK; idx += 32)
            s += g_partials[idx];
        #pragma unroll
        for (int off = 16; off; off >>= 1)
            s += __shfl_down_sync(FULLM, s, off);
        if (tid == 0) {
            res[0] = s;
            atomicSub(&g_count, (unsigned)NBLK);   // replay-safe reset
        }
    }
}

extern "C" void kernel_launch(void* const* d_in, const int* in_sizes, int n_in,
                              void* d_out, int out_size)
{
    const float* out = (const float*)d_in[0];
    const float* dst = (const float*)d_in[1];
    const float* tgt = (const float*)d_in[2];
    (void)in_sizes; (void)n_in; (void)out_size;

    dim3 grid(GXN, GYN, NB);
    loss_kernel<<<grid, TPB>>>(out, dst, tgt, (float*)d_out);
}